// round 1
// baseline (speedup 1.0000x reference)
#include <cuda_runtime.h>
#include <math.h>

// ---------------- scratch (device globals; no allocation allowed) ----------------
__device__ float g_x1[1024 * 16 * 48 * 60];   // conv1 out
__device__ float g_x2[1024 * 16 * 24 * 30];   // conv2 out
__device__ float g_x3[1024 * 16 * 12 * 15];   // conv3 out (= tokens x 2880)
__device__ float g_x [1024 * 256];            // residual stream
__device__ float g_xn[1024 * 256];            // ln1 output
__device__ float g_c [1024 * 768];            // qkv
__device__ float g_h [1024 * 1024];           // ffn hidden
__device__ double g_part[512];                // partial sums / sumsq
__device__ double g_sum, g_sumsq;

// ---------------- conv: stride 2, pad 1, 4x4, relu(out + bias) ----------------
// weights [16][CIN][4][4] cached in SMEM. Each thread: PP output pixels x 16 cout.
template <int CIN, int PP>
__global__ void conv_k(const float* __restrict__ in, const float* __restrict__ w,
                       const float* __restrict__ bias, float* __restrict__ out,
                       int Hin, int Win, int Hout, int Wout) {
    __shared__ float ws[16 * CIN * 16];
    __shared__ float bs[16];
    for (int i = threadIdx.x; i < 16 * CIN * 16; i += blockDim.x) ws[i] = w[i];
    if (threadIdx.x < 16) bs[threadIdx.x] = bias[threadIdx.x];
    __syncthreads();

    const int wg = (Wout + PP - 1) / PP;
    int idx = blockIdx.x * blockDim.x + threadIdx.x;
    int owg = idx % wg;
    int oh  = (idx / wg) % Hout;
    int n   = idx / (wg * Hout);
    if (n >= 1024) return;

    float acc[16][PP];
    #pragma unroll
    for (int co = 0; co < 16; co++)
        #pragma unroll
        for (int p = 0; p < PP; p++) acc[co][p] = 0.f;

    const float* inp = in + n * CIN * Hin * Win;
    for (int ci = 0; ci < CIN; ci++) {
        for (int kh = 0; kh < 4; kh++) {
            int ih = oh * 2 - 1 + kh;
            if (ih < 0 || ih >= Hin) continue;
            const float* irow = inp + (ci * Hin + ih) * Win;
            #pragma unroll
            for (int kw = 0; kw < 4; kw++) {
                float v[PP];
                #pragma unroll
                for (int p = 0; p < PP; p++) {
                    int ow = owg * PP + p;
                    int iw = ow * 2 - 1 + kw;
                    v[p] = (ow < Wout && iw >= 0 && iw < Win) ? irow[iw] : 0.f;
                }
                int widx = (ci * 4 + kh) * 4 + kw;
                #pragma unroll
                for (int co = 0; co < 16; co++) {
                    float wv = ws[co * CIN * 16 + widx];
                    #pragma unroll
                    for (int p = 0; p < PP; p++) acc[co][p] += wv * v[p];
                }
            }
        }
    }
    int obase = n * 16 * Hout * Wout;
    #pragma unroll
    for (int co = 0; co < 16; co++) {
        #pragma unroll
        for (int p = 0; p < PP; p++) {
            int ow = owg * PP + p;
            if (ow < Wout)
                out[obase + (co * Hout + oh) * Wout + ow] = fmaxf(acc[co][p] + bs[co], 0.f);
        }
    }
}

// ---------------- tiled fp32 GEMM: C[M,N] = A[M,K] @ B[K,N] (+epilogue) ----------
// EPI 0: +bias          EPI 1: +bias + pos[(m%512)*N+n]
// EPI 2: gelu(+bias)    EPI 3: +bias + extra[m*N+n] (residual)
template <int EPI>
__global__ void gemm_k(const float* __restrict__ A, const float* __restrict__ B,
                       const float* __restrict__ bias, const float* __restrict__ extra,
                       float* __restrict__ C, int M, int N, int K) {
    __shared__ float As[16][68];
    __shared__ float Bs[16][68];
    const int tid = threadIdx.x;
    const int m0 = blockIdx.y * 64, n0 = blockIdx.x * 64;
    const int ty = tid / 16, tx = tid % 16;
    const int a_row = tid / 4, a_col = (tid % 4) * 4;
    const int b_row = tid / 16, b_col = (tid % 16) * 4;

    float acc[4][4];
    #pragma unroll
    for (int i = 0; i < 4; i++)
        #pragma unroll
        for (int j = 0; j < 4; j++) acc[i][j] = 0.f;

    for (int k0 = 0; k0 < K; k0 += 16) {
        float4 av = *(const float4*)&A[(m0 + a_row) * K + k0 + a_col];
        As[a_col + 0][a_row] = av.x;
        As[a_col + 1][a_row] = av.y;
        As[a_col + 2][a_row] = av.z;
        As[a_col + 3][a_row] = av.w;
        *(float4*)&Bs[b_row][b_col] = *(const float4*)&B[(k0 + b_row) * N + n0 + b_col];
        __syncthreads();
        #pragma unroll
        for (int kk = 0; kk < 16; kk++) {
            float4 a4 = *(const float4*)&As[kk][ty * 4];
            float4 b4 = *(const float4*)&Bs[kk][tx * 4];
            float ar[4] = {a4.x, a4.y, a4.z, a4.w};
            float br[4] = {b4.x, b4.y, b4.z, b4.w};
            #pragma unroll
            for (int i = 0; i < 4; i++)
                #pragma unroll
                for (int j = 0; j < 4; j++) acc[i][j] += ar[i] * br[j];
        }
        __syncthreads();
    }

    #pragma unroll
    for (int i = 0; i < 4; i++) {
        int m = m0 + ty * 4 + i;
        #pragma unroll
        for (int j = 0; j < 4; j++) {
            int n = n0 + tx * 4 + j;
            float v = acc[i][j] + bias[n];
            if (EPI == 1) v += extra[(m & 511) * N + n];
            if (EPI == 2) v = v * normcdff(v);
            if (EPI == 3) v += extra[m * N + n];
            C[m * N + n] = v;
        }
    }
}

// ---------------- layernorm over 256 dims, one block per row ----------------
__global__ void ln_k(const float* __restrict__ in, const float* __restrict__ g,
                     const float* __restrict__ b, float* __restrict__ out) {
    __shared__ float red[256];
    const int t = threadIdx.x;
    const int base = blockIdx.x * 256;
    float v = in[base + t];
    red[t] = v;
    __syncthreads();
    #pragma unroll
    for (int s = 128; s > 0; s >>= 1) {
        if (t < s) red[t] += red[t + s];
        __syncthreads();
    }
    float mu = red[0] * (1.f / 256.f);
    __syncthreads();
    float dv = v - mu;
    red[t] = dv * dv;
    __syncthreads();
    #pragma unroll
    for (int s = 128; s > 0; s >>= 1) {
        if (t < s) red[t] += red[t + s];
        __syncthreads();
    }
    float var = red[0] * (1.f / 256.f);
    out[base + t] = dv * rsqrtf(var + 1e-5f) * g[t] + b[t];
}

// ---------------- causal attention, flash-style, one thread = one query --------
// c: [1024, 768] = [q|k|v] per token. Adds attention output into x (residual).
__global__ void attn_k(const float* __restrict__ c, float* __restrict__ x) {
    __shared__ float Ks[32][32];
    __shared__ float Vs[32][32];
    const int t = threadIdx.x;            // 64 threads
    const int qt = blockIdx.x;            // 8 query tiles of 64
    const int bh = blockIdx.y;            // 16 (b,h)
    const int b = bh >> 3, h = bh & 7;
    const int qi = qt * 64 + t;
    const float* crow = c + (b * 512 + qi) * 768 + h * 32;

    const float SC = 0.17677669529663687f;  // 1/sqrt(32)
    float q[32];
    #pragma unroll
    for (int d4 = 0; d4 < 8; d4++) {
        float4 qv = *(const float4*)(crow + d4 * 4);
        q[4 * d4 + 0] = qv.x * SC;
        q[4 * d4 + 1] = qv.y * SC;
        q[4 * d4 + 2] = qv.z * SC;
        q[4 * d4 + 3] = qv.w * SC;
    }
    float acc[32];
    #pragma unroll
    for (int d = 0; d < 32; d++) acc[d] = 0.f;
    float mrun = -1e30f, l = 0.f;

    const int kend = qt * 64 + 63;
    const int jj = t >> 1, half = (t & 1) * 16;
    for (int kb = 0; kb <= kend; kb += 32) {
        const float* kr = c + (b * 512 + kb + jj) * 768 + 256 + h * 32 + half;
        #pragma unroll
        for (int i4 = 0; i4 < 4; i4++) {
            *(float4*)&Ks[jj][half + i4 * 4] = *(const float4*)(kr + i4 * 4);
            *(float4*)&Vs[jj][half + i4 * 4] = *(const float4*)(kr + 256 + i4 * 4);
        }
        __syncthreads();
        if (kb <= qi) {
            int jmax = qi - kb;
            if (jmax > 31) jmax = 31;
            float sarr[32];
            float tmax = -1e30f;
            #pragma unroll
            for (int j = 0; j < 32; j++) {
                if (j <= jmax) {
                    float s = 0.f;
                    #pragma unroll
                    for (int d = 0; d < 32; d++) s += q[d] * Ks[j][d];
                    sarr[j] = s;
                    tmax = fmaxf(tmax, s);
                }
            }
            float newm = fmaxf(mrun, tmax);
            float alpha = __expf(mrun - newm);
            l *= alpha;
            #pragma unroll
            for (int d = 0; d < 32; d++) acc[d] *= alpha;
            #pragma unroll
            for (int j = 0; j < 32; j++) {
                if (j <= jmax) {
                    float p = __expf(sarr[j] - newm);
                    l += p;
                    #pragma unroll
                    for (int d = 0; d < 32; d++) acc[d] += p * Vs[j][d];
                }
            }
            mrun = newm;
        }
        __syncthreads();
    }
    float inv = 1.f / l;
    float* xr = x + (b * 512 + qi) * 256 + h * 32;
    #pragma unroll
    for (int d = 0; d < 32; d++) xr[d] += acc[d] * inv;
}

// ---------------- deterministic global mean/std (ddof=1) + normalize ------------
__global__ void reduce_k(const float* __restrict__ e) {
    __shared__ double s1[256], s2[256];
    const int t = threadIdx.x;
    double s = 0.0, ss = 0.0;
    for (int i = blockIdx.x * 256 + t; i < 262144; i += 256 * 256) {
        double v = (double)e[i];
        s += v;
        ss += v * v;
    }
    s1[t] = s;
    s2[t] = ss;
    __syncthreads();
    for (int k = 128; k > 0; k >>= 1) {
        if (t < k) { s1[t] += s1[t + k]; s2[t] += s2[t + k]; }
        __syncthreads();
    }
    if (t == 0) { g_part[blockIdx.x] = s1[0]; g_part[256 + blockIdx.x] = s2[0]; }
}

__global__ void stats_k() {
    __shared__ double s1[256], s2[256];
    const int t = threadIdx.x;
    s1[t] = g_part[t];
    s2[t] = g_part[256 + t];
    __syncthreads();
    for (int k = 128; k > 0; k >>= 1) {
        if (t < k) { s1[t] += s1[t + k]; s2[t] += s2[t + k]; }
        __syncthreads();
    }
    if (t == 0) { g_sum = s1[0]; g_sumsq = s2[0]; }
}

__global__ void norm_k(float* e) {
    const double n = 262144.0;
    double mu = g_sum / n;
    double var = (g_sumsq - n * mu * mu) / (n - 1.0);
    float inv = (float)(1.0 / sqrt(var));
    float fmu = (float)mu;
    int i = blockIdx.x * 256 + threadIdx.x;
    e[i] = (e[i] - fmu) * inv + 1e-10f;
}

// ---------------- launch ----------------
extern "C" void kernel_launch(void* const* d_in, const int* in_sizes, int n_in,
                              void* d_out, int out_size) {
    const float* state   = (const float*)d_in[0];
    const float* conv_w1 = (const float*)d_in[1];
    const float* conv_b1 = (const float*)d_in[2];
    const float* conv_w2 = (const float*)d_in[3];
    const float* conv_b2 = (const float*)d_in[4];
    const float* conv_w3 = (const float*)d_in[5];
    const float* conv_b3 = (const float*)d_in[6];
    const float* pre_w   = (const float*)d_in[7];
    const float* pre_b   = (const float*)d_in[8];
    const float* pos_w   = (const float*)d_in[9];
    const float* ln1_g   = (const float*)d_in[10];
    const float* ln1_b   = (const float*)d_in[11];
    const float* enc_w   = (const float*)d_in[12];
    const float* enc_b   = (const float*)d_in[13];
    const float* ln2_g   = (const float*)d_in[14];
    const float* ln2_b   = (const float*)d_in[15];
    const float* ffn_w1  = (const float*)d_in[16];
    const float* ffn_b1  = (const float*)d_in[17];
    const float* ffn_w2  = (const float*)d_in[18];
    const float* ffn_b2  = (const float*)d_in[19];
    const float* emb_w   = (const float*)d_in[20];
    const float* emb_b   = (const float*)d_in[21];
    float* out = (float*)d_out;

    float *x1, *x2, *x3, *x, *xn, *cb, *hb;
    cudaGetSymbolAddress((void**)&x1, g_x1);
    cudaGetSymbolAddress((void**)&x2, g_x2);
    cudaGetSymbolAddress((void**)&x3, g_x3);
    cudaGetSymbolAddress((void**)&x,  g_x);
    cudaGetSymbolAddress((void**)&xn, g_xn);
    cudaGetSymbolAddress((void**)&cb, g_c);
    cudaGetSymbolAddress((void**)&hb, g_h);

    // conv stem: 96x120 -> 48x60 -> 24x30 -> 12x15
    conv_k<3, 4><<<2880, 256>>>(state, conv_w1, conv_b1, x1, 96, 120, 48, 60);
    conv_k<16, 4><<<768, 256>>>(x1, conv_w2, conv_b2, x2, 48, 60, 24, 30);
    conv_k<16, 4><<<192, 256>>>(x2, conv_w3, conv_b3, x3, 24, 30, 12, 15);

    // pre-projection + positional
    gemm_k<1><<<dim3(4, 16), 256>>>(x3, pre_w, pre_b, pos_w, x, 1024, 256, 2880);

    for (int k = 0; k < 4; k++) {
        ln_k<<<1024, 256>>>(x, ln1_g + k * 256, ln1_b + k * 256, xn);
        gemm_k<0><<<dim3(12, 16), 256>>>(xn, enc_w + k * 256 * 768, enc_b + k * 768,
                                         nullptr, cb, 1024, 768, 256);
        attn_k<<<dim3(8, 16), 64>>>(cb, x);
        ln_k<<<1024, 256>>>(x, ln2_g + k * 256, ln2_b + k * 256, x);
        gemm_k<2><<<dim3(16, 16), 256>>>(x, ffn_w1 + k * 256 * 1024, ffn_b1 + k * 1024,
                                         nullptr, hb, 1024, 1024, 256);
        gemm_k<3><<<dim3(4, 16), 256>>>(hb, ffn_w2 + k * 1024 * 256, ffn_b2 + k * 256,
                                        x, x, 1024, 256, 1024);
    }

    gemm_k<0><<<dim3(4, 16), 256>>>(x, emb_w, emb_b, nullptr, out, 1024, 256, 256);

    reduce_k<<<256, 256>>>(out);
    stats_k<<<1, 256>>>();
    norm_k<<<1024, 256>>>(out);
}

// round 2
// speedup vs baseline: 1.2626x; 1.2626x over previous
#include <cuda_runtime.h>
#include <math.h>

// ---------------- scratch (device globals; no allocation allowed) ----------------
__device__ float g_x1[1024 * 16 * 48 * 60];   // conv1 out
__device__ float g_x2[1024 * 16 * 24 * 30];   // conv2 out
__device__ float g_x3[1024 * 16 * 12 * 15];   // conv3 out (= tokens x 2880)
__device__ float g_x [1024 * 256];            // residual stream
__device__ float g_xn[1024 * 256];            // ln1 output
__device__ float g_c [1024 * 768];            // qkv
__device__ float g_h [1024 * 1024];           // ffn hidden
__device__ double g_part[512];                // partial sums / sumsq
__device__ double g_sum, g_sumsq;

// ---------------- conv: stride 2, pad 1, 4x4, relu(out + bias) ----------------
template <int CIN, int PP>
__global__ void conv_k(const float* __restrict__ in, const float* __restrict__ w,
                       const float* __restrict__ bias, float* __restrict__ out,
                       int Hin, int Win, int Hout, int Wout) {
    __shared__ float ws[16 * CIN * 16];
    __shared__ float bs[16];
    for (int i = threadIdx.x; i < 16 * CIN * 16; i += blockDim.x) ws[i] = w[i];
    if (threadIdx.x < 16) bs[threadIdx.x] = bias[threadIdx.x];
    __syncthreads();

    const int wg = (Wout + PP - 1) / PP;
    int idx = blockIdx.x * blockDim.x + threadIdx.x;
    int owg = idx % wg;
    int oh  = (idx / wg) % Hout;
    int n   = idx / (wg * Hout);
    if (n >= 1024) return;

    float acc[16][PP];
    #pragma unroll
    for (int co = 0; co < 16; co++)
        #pragma unroll
        for (int p = 0; p < PP; p++) acc[co][p] = 0.f;

    const float* inp = in + n * CIN * Hin * Win;
    for (int ci = 0; ci < CIN; ci++) {
        for (int kh = 0; kh < 4; kh++) {
            int ih = oh * 2 - 1 + kh;
            if (ih < 0 || ih >= Hin) continue;
            const float* irow = inp + (ci * Hin + ih) * Win;
            #pragma unroll
            for (int kw = 0; kw < 4; kw++) {
                float v[PP];
                #pragma unroll
                for (int p = 0; p < PP; p++) {
                    int ow = owg * PP + p;
                    int iw = ow * 2 - 1 + kw;
                    v[p] = (ow < Wout && iw >= 0 && iw < Win) ? irow[iw] : 0.f;
                }
                int widx = (ci * 4 + kh) * 4 + kw;
                #pragma unroll
                for (int co = 0; co < 16; co++) {
                    float wv = ws[co * CIN * 16 + widx];
                    #pragma unroll
                    for (int p = 0; p < PP; p++) acc[co][p] += wv * v[p];
                }
            }
        }
    }
    int obase = n * 16 * Hout * Wout;
    #pragma unroll
    for (int co = 0; co < 16; co++) {
        #pragma unroll
        for (int p = 0; p < PP; p++) {
            int ow = owg * PP + p;
            if (ow < Wout)
                out[obase + (co * Hout + oh) * Wout + ow] = fmaxf(acc[co][p] + bs[co], 0.f);
        }
    }
}

// ---------------- tf32 tensor-core GEMM ----------------
// C[M,N] = A[M,K] @ B[K,N] (+epilogue). Block tile 32x64, 2 warps (warp tile 32x32).
// EPI 0: +bias   EPI 1: +bias+pos[(m%512)*N+n]   EPI 2: gelu(+bias)   EPI 3: +bias+extra[m*N+n]
__device__ __forceinline__ unsigned f2tf(float f) {
    unsigned u;
    asm("cvt.rna.tf32.f32 %0, %1;" : "=r"(u) : "f"(f));
    return u;
}
__device__ __forceinline__ void mma_tf32(float c[4], unsigned a0, unsigned a1,
                                         unsigned a2, unsigned a3,
                                         unsigned b0, unsigned b1) {
    asm volatile(
        "mma.sync.aligned.m16n8k8.row.col.f32.tf32.tf32.f32 "
        "{%0,%1,%2,%3}, {%4,%5,%6,%7}, {%8,%9}, {%0,%1,%2,%3};\n"
        : "+f"(c[0]), "+f"(c[1]), "+f"(c[2]), "+f"(c[3])
        : "r"(a0), "r"(a1), "r"(a2), "r"(a3), "r"(b0), "r"(b1));
}

template <int EPI>
__global__ void __launch_bounds__(64) gemm_k(
    const float* __restrict__ A, const float* __restrict__ B,
    const float* __restrict__ bias, const float* __restrict__ extra,
    float* __restrict__ C, int M, int N, int K) {
    __shared__ unsigned As[32][36];   // [m][k] tf32 bits
    __shared__ unsigned Bs[32][68];   // [k][n] tf32 bits

    const int t = threadIdx.x;
    const int m0 = blockIdx.y * 32, n0 = blockIdx.x * 64;
    const int warp = t >> 5, lane = t & 31;
    const int g = lane >> 2, tig = lane & 3;
    const int nwb = warp * 32;        // warp's n offset inside tile

    float acc[2][4][4];
    #pragma unroll
    for (int mf = 0; mf < 2; mf++)
        #pragma unroll
        for (int nf = 0; nf < 4; nf++)
            #pragma unroll
            for (int r = 0; r < 4; r++) acc[mf][nf][r] = 0.f;

    const int NC = K >> 5;            // K-chunks of 32
    float4 ra[4], rb[8];

    // prefetch chunk 0
    {
        const float* Ab = A + m0 * K;
        const float* Bb = B + n0;
        #pragma unroll
        for (int j = 0; j < 4; j++) {
            int idx = t + 64 * j;
            ra[j] = *(const float4*)&Ab[(idx >> 3) * K + (idx & 7) * 4];
        }
        #pragma unroll
        for (int j = 0; j < 8; j++) {
            int idx = t + 64 * j;
            rb[j] = *(const float4*)&Bb[(idx >> 4) * N + (idx & 15) * 4];
        }
    }

    for (int c = 0; c < NC; c++) {
        // stage prefetched regs to SMEM (tf32-converted)
        #pragma unroll
        for (int j = 0; j < 4; j++) {
            int idx = t + 64 * j;
            unsigned* p = &As[idx >> 3][(idx & 7) * 4];
            p[0] = f2tf(ra[j].x); p[1] = f2tf(ra[j].y);
            p[2] = f2tf(ra[j].z); p[3] = f2tf(ra[j].w);
        }
        #pragma unroll
        for (int j = 0; j < 8; j++) {
            int idx = t + 64 * j;
            unsigned* p = &Bs[idx >> 4][(idx & 15) * 4];
            p[0] = f2tf(rb[j].x); p[1] = f2tf(rb[j].y);
            p[2] = f2tf(rb[j].z); p[3] = f2tf(rb[j].w);
        }
        __syncthreads();

        // prefetch next chunk
        if (c + 1 < NC) {
            int k0 = (c + 1) * 32;
            const float* Ab = A + m0 * K + k0;
            const float* Bb = B + k0 * N + n0;
            #pragma unroll
            for (int j = 0; j < 4; j++) {
                int idx = t + 64 * j;
                ra[j] = *(const float4*)&Ab[(idx >> 3) * K + (idx & 7) * 4];
            }
            #pragma unroll
            for (int j = 0; j < 8; j++) {
                int idx = t + 64 * j;
                rb[j] = *(const float4*)&Bb[(idx >> 4) * N + (idx & 15) * 4];
            }
        }

        // compute 4 k-steps of 8
        #pragma unroll
        for (int ks = 0; ks < 4; ks++) {
            int k8 = ks * 8;
            unsigned a[2][4];
            #pragma unroll
            for (int mf = 0; mf < 2; mf++) {
                int mb = mf * 16;
                a[mf][0] = As[mb + g][k8 + tig];
                a[mf][1] = As[mb + g + 8][k8 + tig];
                a[mf][2] = As[mb + g][k8 + tig + 4];
                a[mf][3] = As[mb + g + 8][k8 + tig + 4];
            }
            unsigned b[4][2];
            #pragma unroll
            for (int nf = 0; nf < 4; nf++) {
                int nc = nwb + nf * 8 + g;
                b[nf][0] = Bs[k8 + tig][nc];
                b[nf][1] = Bs[k8 + tig + 4][nc];
            }
            #pragma unroll
            for (int mf = 0; mf < 2; mf++)
                #pragma unroll
                for (int nf = 0; nf < 4; nf++)
                    mma_tf32(acc[mf][nf], a[mf][0], a[mf][1], a[mf][2], a[mf][3],
                             b[nf][0], b[nf][1]);
        }
        __syncthreads();
    }

    // epilogue: c0,c1 -> (row g, cols 2t,2t+1); c2,c3 -> (row g+8)
    #pragma unroll
    for (int mf = 0; mf < 2; mf++) {
        #pragma unroll
        for (int half = 0; half < 2; half++) {
            int m = m0 + mf * 16 + g + half * 8;
            #pragma unroll
            for (int nf = 0; nf < 4; nf++) {
                int n = n0 + nwb + nf * 8 + 2 * tig;
                float v0 = acc[mf][nf][2 * half + 0] + bias[n];
                float v1 = acc[mf][nf][2 * half + 1] + bias[n + 1];
                if (EPI == 1) {
                    v0 += extra[(m & 511) * N + n];
                    v1 += extra[(m & 511) * N + n + 1];
                }
                if (EPI == 2) { v0 = v0 * normcdff(v0); v1 = v1 * normcdff(v1); }
                if (EPI == 3) { v0 += extra[m * N + n]; v1 += extra[m * N + n + 1]; }
                *(float2*)&C[m * N + n] = make_float2(v0, v1);
            }
        }
    }
}

// ---------------- layernorm over 256 dims, one block per row ----------------
__global__ void ln_k(const float* __restrict__ in, const float* __restrict__ g,
                     const float* __restrict__ b, float* __restrict__ out) {
    __shared__ float red[256];
    const int t = threadIdx.x;
    const int base = blockIdx.x * 256;
    float v = in[base + t];
    red[t] = v;
    __syncthreads();
    #pragma unroll
    for (int s = 128; s > 0; s >>= 1) {
        if (t < s) red[t] += red[t + s];
        __syncthreads();
    }
    float mu = red[0] * (1.f / 256.f);
    __syncthreads();
    float dv = v - mu;
    red[t] = dv * dv;
    __syncthreads();
    #pragma unroll
    for (int s = 128; s > 0; s >>= 1) {
        if (t < s) red[t] += red[t + s];
        __syncthreads();
    }
    float var = red[0] * (1.f / 256.f);
    out[base + t] = dv * rsqrtf(var + 1e-5f) * g[t] + b[t];
}

// ---------------- causal attention, flash-style, one thread = one query --------
__global__ void attn_k(const float* __restrict__ c, float* __restrict__ x) {
    __shared__ float Ks[32][32];
    __shared__ float Vs[32][32];
    const int t = threadIdx.x;            // 64 threads
    const int qt = blockIdx.x;            // 8 query tiles of 64
    const int bh = blockIdx.y;            // 16 (b,h)
    const int b = bh >> 3, h = bh & 7;
    const int qi = qt * 64 + t;
    const float* crow = c + (b * 512 + qi) * 768 + h * 32;

    const float SC = 0.17677669529663687f;  // 1/sqrt(32)
    float q[32];
    #pragma unroll
    for (int d4 = 0; d4 < 8; d4++) {
        float4 qv = *(const float4*)(crow + d4 * 4);
        q[4 * d4 + 0] = qv.x * SC;
        q[4 * d4 + 1] = qv.y * SC;
        q[4 * d4 + 2] = qv.z * SC;
        q[4 * d4 + 3] = qv.w * SC;
    }
    float acc[32];
    #pragma unroll
    for (int d = 0; d < 32; d++) acc[d] = 0.f;
    float mrun = -1e30f, l = 0.f;

    const int kend = qt * 64 + 63;
    const int jj = t >> 1, half = (t & 1) * 16;
    for (int kb = 0; kb <= kend; kb += 32) {
        const float* kr = c + (b * 512 + kb + jj) * 768 + 256 + h * 32 + half;
        #pragma unroll
        for (int i4 = 0; i4 < 4; i4++) {
            *(float4*)&Ks[jj][half + i4 * 4] = *(const float4*)(kr + i4 * 4);
            *(float4*)&Vs[jj][half + i4 * 4] = *(const float4*)(kr + 256 + i4 * 4);
        }
        __syncthreads();
        if (kb <= qi) {
            int jmax = qi - kb;
            if (jmax > 31) jmax = 31;
            float sarr[32];
            float tmax = -1e30f;
            #pragma unroll
            for (int j = 0; j < 32; j++) {
                if (j <= jmax) {
                    float s = 0.f;
                    #pragma unroll
                    for (int d = 0; d < 32; d++) s += q[d] * Ks[j][d];
                    sarr[j] = s;
                    tmax = fmaxf(tmax, s);
                }
            }
            float newm = fmaxf(mrun, tmax);
            float alpha = __expf(mrun - newm);
            l *= alpha;
            #pragma unroll
            for (int d = 0; d < 32; d++) acc[d] *= alpha;
            #pragma unroll
            for (int j = 0; j < 32; j++) {
                if (j <= jmax) {
                    float p = __expf(sarr[j] - newm);
                    l += p;
                    #pragma unroll
                    for (int d = 0; d < 32; d++) acc[d] += p * Vs[j][d];
                }
            }
            mrun = newm;
        }
        __syncthreads();
    }
    float inv = 1.f / l;
    float* xr = x + (b * 512 + qi) * 256 + h * 32;
    #pragma unroll
    for (int d = 0; d < 32; d++) xr[d] += acc[d] * inv;
}

// ---------------- deterministic global mean/std (ddof=1) + normalize ------------
__global__ void reduce_k(const float* __restrict__ e) {
    __shared__ double s1[256], s2[256];
    const int t = threadIdx.x;
    double s = 0.0, ss = 0.0;
    for (int i = blockIdx.x * 256 + t; i < 262144; i += 256 * 256) {
        double v = (double)e[i];
        s += v;
        ss += v * v;
    }
    s1[t] = s;
    s2[t] = ss;
    __syncthreads();
    for (int k = 128; k > 0; k >>= 1) {
        if (t < k) { s1[t] += s1[t + k]; s2[t] += s2[t + k]; }
        __syncthreads();
    }
    if (t == 0) { g_part[blockIdx.x] = s1[0]; g_part[256 + blockIdx.x] = s2[0]; }
}

__global__ void stats_k() {
    __shared__ double s1[256], s2[256];
    const int t = threadIdx.x;
    s1[t] = g_part[t];
    s2[t] = g_part[256 + t];
    __syncthreads();
    for (int k = 128; k > 0; k >>= 1) {
        if (t < k) { s1[t] += s1[t + k]; s2[t] += s2[t + k]; }
        __syncthreads();
    }
    if (t == 0) { g_sum = s1[0]; g_sumsq = s2[0]; }
}

__global__ void norm_k(float* e) {
    const double n = 262144.0;
    double mu = g_sum / n;
    double var = (g_sumsq - n * mu * mu) / (n - 1.0);
    float inv = (float)(1.0 / sqrt(var));
    float fmu = (float)mu;
    int i = blockIdx.x * 256 + threadIdx.x;
    e[i] = (e[i] - fmu) * inv + 1e-10f;
}

// ---------------- launch ----------------
extern "C" void kernel_launch(void* const* d_in, const int* in_sizes, int n_in,
                              void* d_out, int out_size) {
    const float* state   = (const float*)d_in[0];
    const float* conv_w1 = (const float*)d_in[1];
    const float* conv_b1 = (const float*)d_in[2];
    const float* conv_w2 = (const float*)d_in[3];
    const float* conv_b2 = (const float*)d_in[4];
    const float* conv_w3 = (const float*)d_in[5];
    const float* conv_b3 = (const float*)d_in[6];
    const float* pre_w   = (const float*)d_in[7];
    const float* pre_b   = (const float*)d_in[8];
    const float* pos_w   = (const float*)d_in[9];
    const float* ln1_g   = (const float*)d_in[10];
    const float* ln1_b   = (const float*)d_in[11];
    const float* enc_w   = (const float*)d_in[12];
    const float* enc_b   = (const float*)d_in[13];
    const float* ln2_g   = (const float*)d_in[14];
    const float* ln2_b   = (const float*)d_in[15];
    const float* ffn_w1  = (const float*)d_in[16];
    const float* ffn_b1  = (const float*)d_in[17];
    const float* ffn_w2  = (const float*)d_in[18];
    const float* ffn_b2  = (const float*)d_in[19];
    const float* emb_w   = (const float*)d_in[20];
    const float* emb_b   = (const float*)d_in[21];
    float* out = (float*)d_out;

    float *x1, *x2, *x3, *x, *xn, *cb, *hb;
    cudaGetSymbolAddress((void**)&x1, g_x1);
    cudaGetSymbolAddress((void**)&x2, g_x2);
    cudaGetSymbolAddress((void**)&x3, g_x3);
    cudaGetSymbolAddress((void**)&x,  g_x);
    cudaGetSymbolAddress((void**)&xn, g_xn);
    cudaGetSymbolAddress((void**)&cb, g_c);
    cudaGetSymbolAddress((void**)&hb, g_h);

    // conv stem: 96x120 -> 48x60 -> 24x30 -> 12x15
    conv_k<3, 4><<<2880, 256>>>(state, conv_w1, conv_b1, x1, 96, 120, 48, 60);
    conv_k<16, 4><<<768, 256>>>(x1, conv_w2, conv_b2, x2, 48, 60, 24, 30);
    conv_k<16, 4><<<192, 256>>>(x2, conv_w3, conv_b3, x3, 24, 30, 12, 15);

    // pre-projection + positional  (tf32 tensor cores)
    gemm_k<1><<<dim3(4, 32), 64>>>(x3, pre_w, pre_b, pos_w, x, 1024, 256, 2880);

    for (int k = 0; k < 4; k++) {
        ln_k<<<1024, 256>>>(x, ln1_g + k * 256, ln1_b + k * 256, xn);
        gemm_k<0><<<dim3(12, 32), 64>>>(xn, enc_w + k * 256 * 768, enc_b + k * 768,
                                        nullptr, cb, 1024, 768, 256);
        attn_k<<<dim3(8, 16), 64>>>(cb, x);
        ln_k<<<1024, 256>>>(x, ln2_g + k * 256, ln2_b + k * 256, x);
        gemm_k<2><<<dim3(16, 32), 64>>>(x, ffn_w1 + k * 256 * 1024, ffn_b1 + k * 1024,
                                        nullptr, hb, 1024, 1024, 256);
        gemm_k<3><<<dim3(4, 32), 64>>>(hb, ffn_w2 + k * 1024 * 256, ffn_b2 + k * 256,
                                       x, x, 1024, 256, 1024);
    }

    gemm_k<0><<<dim3(4, 32), 64>>>(x, emb_w, emb_b, nullptr, out, 1024, 256, 256);

    reduce_k<<<256, 256>>>(out);
    stats_k<<<1, 256>>>();
    norm_k<<<1024, 256>>>(out);
}

// round 3
// speedup vs baseline: 1.4615x; 1.1575x over previous
#include <cuda_runtime.h>
#include <math.h>

// ---------------- scratch (device globals; no allocation allowed) ----------------
__device__ float g_x1[1024 * 16 * 48 * 60];   // conv1 out
__device__ float g_x2[1024 * 16 * 24 * 30];   // conv2 out
__device__ float g_x3[1024 * 16 * 12 * 15];   // conv3 out (= tokens x 2880)
__device__ float g_x [1024 * 256];            // residual stream
__device__ float g_xn[1024 * 256];            // ln1 output
__device__ float g_c [1024 * 768];            // qkv
__device__ float g_h [1024 * 1024];           // ffn hidden
__device__ double g_part[512];                // partial sums / sumsq
__device__ double g_sum, g_sumsq;

// ---------------- conv: stride 2, pad 1, 4x4, relu(out + bias) ----------------
// Weights transposed in SMEM: ws[tap][cout] so 16 cout weights load as 4x LDS.128.
// Input window (10 floats) preloaded per (ci, ih), shared across (kw, p).
template <int CIN>
__global__ void __launch_bounds__(256) conv_k(
    const float* __restrict__ in, const float* __restrict__ w,
    const float* __restrict__ bias, float* __restrict__ out,
    int Hin, int Win, int Hout, int Wout) {
    __shared__ float ws[CIN * 16 * 16];   // [widx][co]
    __shared__ float bs[16];
    for (int i = threadIdx.x; i < CIN * 16 * 16; i += blockDim.x) {
        int widx = i >> 4, co = i & 15;
        ws[i] = w[co * CIN * 16 + widx];
    }
    if (threadIdx.x < 16) bs[threadIdx.x] = bias[threadIdx.x];
    __syncthreads();

    const int wg = (Wout + 3) >> 2;
    int idx = blockIdx.x * blockDim.x + threadIdx.x;
    int owg = idx % wg;
    int oh  = (idx / wg) % Hout;
    int n   = idx / (wg * Hout);
    if (n >= 1024) return;

    float acc[16][4];
    #pragma unroll
    for (int co = 0; co < 16; co++)
        #pragma unroll
        for (int p = 0; p < 4; p++) acc[co][p] = 0.f;

    const float* inp = in + n * CIN * Hin * Win;
    const int iwb = owg * 8 - 1;
    #pragma unroll 1
    for (int ci = 0; ci < CIN; ci++) {
        #pragma unroll
        for (int kh = 0; kh < 4; kh++) {
            int ih = oh * 2 - 1 + kh;
            if (ih < 0 || ih >= Hin) continue;
            const float* irow = inp + (ci * Hin + ih) * Win;
            float vin[10];
            #pragma unroll
            for (int j = 0; j < 10; j++) {
                int iw = iwb + j;
                vin[j] = (iw >= 0 && iw < Win) ? irow[iw] : 0.f;
            }
            #pragma unroll
            for (int kw = 0; kw < 4; kw++) {
                int widx = (ci * 4 + kh) * 4 + kw;
                const float4* w4 = (const float4*)&ws[widx << 4];
                float4 w0 = w4[0], w1 = w4[1], w2 = w4[2], w3 = w4[3];
                #pragma unroll
                for (int p = 0; p < 4; p++) {
                    float v = vin[2 * p + kw];
                    acc[0][p]  += w0.x * v; acc[1][p]  += w0.y * v;
                    acc[2][p]  += w0.z * v; acc[3][p]  += w0.w * v;
                    acc[4][p]  += w1.x * v; acc[5][p]  += w1.y * v;
                    acc[6][p]  += w1.z * v; acc[7][p]  += w1.w * v;
                    acc[8][p]  += w2.x * v; acc[9][p]  += w2.y * v;
                    acc[10][p] += w2.z * v; acc[11][p] += w2.w * v;
                    acc[12][p] += w3.x * v; acc[13][p] += w3.y * v;
                    acc[14][p] += w3.z * v; acc[15][p] += w3.w * v;
                }
            }
        }
    }
    int obase = n * 16 * Hout * Wout;
    #pragma unroll
    for (int co = 0; co < 16; co++) {
        #pragma unroll
        for (int p = 0; p < 4; p++) {
            int ow = owg * 4 + p;
            if (ow < Wout)
                out[obase + (co * Hout + oh) * Wout + ow] = fmaxf(acc[co][p] + bs[co], 0.f);
        }
    }
}

// ---------------- tf32 tensor-core GEMM ----------------
// Block tile 32x64, 256 threads (8 warps as 2x4), warp tile 16x16.
// EPI 0: +bias   EPI 1: +bias+pos[(m%512)*N+n]   EPI 2: gelu(+bias)   EPI 3: +bias+extra
__device__ __forceinline__ unsigned f2tf(float f) {
    unsigned u;
    asm("cvt.rna.tf32.f32 %0, %1;" : "=r"(u) : "f"(f));
    return u;
}
__device__ __forceinline__ void mma_tf32(float c[4], unsigned a0, unsigned a1,
                                         unsigned a2, unsigned a3,
                                         unsigned b0, unsigned b1) {
    asm volatile(
        "mma.sync.aligned.m16n8k8.row.col.f32.tf32.tf32.f32 "
        "{%0,%1,%2,%3}, {%4,%5,%6,%7}, {%8,%9}, {%0,%1,%2,%3};\n"
        : "+f"(c[0]), "+f"(c[1]), "+f"(c[2]), "+f"(c[3])
        : "r"(a0), "r"(a1), "r"(a2), "r"(a3), "r"(b0), "r"(b1));
}

template <int EPI>
__global__ void __launch_bounds__(256) gemm_k(
    const float* __restrict__ A, const float* __restrict__ B,
    const float* __restrict__ bias, const float* __restrict__ extra,
    float* __restrict__ C, int M, int N, int K) {
    __shared__ unsigned As[32][36];   // [m][k]
    __shared__ unsigned Bs[32][68];   // [k][n]

    const int t = threadIdx.x;
    const int m0 = blockIdx.y * 32, n0 = blockIdx.x * 64;
    const int warp = t >> 5, lane = t & 31;
    const int g = lane >> 2, tig = lane & 3;
    const int wm = (warp >> 2) * 16;      // 0 or 16
    const int wn = (warp & 3) * 16;       // 0,16,32,48

    float acc[2][4];
    #pragma unroll
    for (int nf = 0; nf < 2; nf++)
        #pragma unroll
        for (int r = 0; r < 4; r++) acc[nf][r] = 0.f;

    const int a_row = t >> 3, a_col = (t & 7) * 4;     // A: 32x32, 1 float4/thread
    const int b_row = t >> 4, b_col = (t & 15) * 4;    // B: 32x64, 2 float4/thread
    const int NC = K >> 5;
    float4 ra, rb0, rb1;

    ra  = *(const float4*)&A[(m0 + a_row) * K + a_col];
    rb0 = *(const float4*)&B[b_row * N + n0 + b_col];
    rb1 = *(const float4*)&B[(b_row + 16) * N + n0 + b_col];

    for (int c = 0; c < NC; c++) {
        {
            unsigned* p = &As[a_row][a_col];
            p[0] = f2tf(ra.x); p[1] = f2tf(ra.y); p[2] = f2tf(ra.z); p[3] = f2tf(ra.w);
            unsigned* q0 = &Bs[b_row][b_col];
            q0[0] = f2tf(rb0.x); q0[1] = f2tf(rb0.y); q0[2] = f2tf(rb0.z); q0[3] = f2tf(rb0.w);
            unsigned* q1 = &Bs[b_row + 16][b_col];
            q1[0] = f2tf(rb1.x); q1[1] = f2tf(rb1.y); q1[2] = f2tf(rb1.z); q1[3] = f2tf(rb1.w);
        }
        __syncthreads();

        if (c + 1 < NC) {
            int k0 = (c + 1) * 32;
            ra  = *(const float4*)&A[(m0 + a_row) * K + k0 + a_col];
            rb0 = *(const float4*)&B[(k0 + b_row) * N + n0 + b_col];
            rb1 = *(const float4*)&B[(k0 + b_row + 16) * N + n0 + b_col];
        }

        #pragma unroll
        for (int ks = 0; ks < 4; ks++) {
            int k8 = ks * 8;
            unsigned a0 = As[wm + g][k8 + tig];
            unsigned a1 = As[wm + g + 8][k8 + tig];
            unsigned a2 = As[wm + g][k8 + tig + 4];
            unsigned a3 = As[wm + g + 8][k8 + tig + 4];
            #pragma unroll
            for (int nf = 0; nf < 2; nf++) {
                int nc = wn + nf * 8 + g;
                unsigned b0 = Bs[k8 + tig][nc];
                unsigned b1 = Bs[k8 + tig + 4][nc];
                mma_tf32(acc[nf], a0, a1, a2, a3, b0, b1);
            }
        }
        __syncthreads();
    }

    #pragma unroll
    for (int half = 0; half < 2; half++) {
        int m = m0 + wm + g + half * 8;
        #pragma unroll
        for (int nf = 0; nf < 2; nf++) {
            int n = n0 + wn + nf * 8 + 2 * tig;
            float v0 = acc[nf][2 * half + 0] + bias[n];
            float v1 = acc[nf][2 * half + 1] + bias[n + 1];
            if (EPI == 1) {
                v0 += extra[(m & 511) * N + n];
                v1 += extra[(m & 511) * N + n + 1];
            }
            if (EPI == 2) { v0 = v0 * normcdff(v0); v1 = v1 * normcdff(v1); }
            if (EPI == 3) { v0 += extra[m * N + n]; v1 += extra[m * N + n + 1]; }
            *(float2*)&C[m * N + n] = make_float2(v0, v1);
        }
    }
}

// ---------------- layernorm over 256 dims, one block per row ----------------
__global__ void ln_k(const float* __restrict__ in, const float* __restrict__ g,
                     const float* __restrict__ b, float* __restrict__ out) {
    __shared__ float red[256];
    const int t = threadIdx.x;
    const int base = blockIdx.x * 256;
    float v = in[base + t];
    red[t] = v;
    __syncthreads();
    #pragma unroll
    for (int s = 128; s > 0; s >>= 1) {
        if (t < s) red[t] += red[t + s];
        __syncthreads();
    }
    float mu = red[0] * (1.f / 256.f);
    __syncthreads();
    float dv = v - mu;
    red[t] = dv * dv;
    __syncthreads();
    #pragma unroll
    for (int s = 128; s > 0; s >>= 1) {
        if (t < s) red[t] += red[t + s];
        __syncthreads();
    }
    float var = red[0] * (1.f / 256.f);
    out[base + t] = dv * rsqrtf(var + 1e-5f) * g[t] + b[t];
}

// ---------------- causal attention, flash-style, one thread = one query --------
__global__ void attn_k(const float* __restrict__ c, float* __restrict__ x) {
    __shared__ float Ks[32][32];
    __shared__ float Vs[32][32];
    const int t = threadIdx.x;            // 64 threads
    const int qt = blockIdx.x;            // 8 query tiles of 64
    const int bh = blockIdx.y;            // 16 (b,h)
    const int b = bh >> 3, h = bh & 7;
    const int qi = qt * 64 + t;
    const float* crow = c + (b * 512 + qi) * 768 + h * 32;

    const float SC = 0.17677669529663687f;  // 1/sqrt(32)
    float q[32];
    #pragma unroll
    for (int d4 = 0; d4 < 8; d4++) {
        float4 qv = *(const float4*)(crow + d4 * 4);
        q[4 * d4 + 0] = qv.x * SC;
        q[4 * d4 + 1] = qv.y * SC;
        q[4 * d4 + 2] = qv.z * SC;
        q[4 * d4 + 3] = qv.w * SC;
    }
    float acc[32];
    #pragma unroll
    for (int d = 0; d < 32; d++) acc[d] = 0.f;
    float mrun = -1e30f, l = 0.f;

    const int kend = qt * 64 + 63;
    const int jj = t >> 1, half = (t & 1) * 16;
    for (int kb = 0; kb <= kend; kb += 32) {
        const float* kr = c + (b * 512 + kb + jj) * 768 + 256 + h * 32 + half;
        #pragma unroll
        for (int i4 = 0; i4 < 4; i4++) {
            *(float4*)&Ks[jj][half + i4 * 4] = *(const float4*)(kr + i4 * 4);
            *(float4*)&Vs[jj][half + i4 * 4] = *(const float4*)(kr + 256 + i4 * 4);
        }
        __syncthreads();
        if (kb <= qi) {
            int jmax = qi - kb;
            if (jmax > 31) jmax = 31;
            float sarr[32];
            float tmax = -1e30f;
            #pragma unroll
            for (int j = 0; j < 32; j++) {
                if (j <= jmax) {
                    float s = 0.f;
                    #pragma unroll
                    for (int d = 0; d < 32; d++) s += q[d] * Ks[j][d];
                    sarr[j] = s;
                    tmax = fmaxf(tmax, s);
                }
            }
            float newm = fmaxf(mrun, tmax);
            float alpha = __expf(mrun - newm);
            l *= alpha;
            #pragma unroll
            for (int d = 0; d < 32; d++) acc[d] *= alpha;
            #pragma unroll
            for (int j = 0; j < 32; j++) {
                if (j <= jmax) {
                    float p = __expf(sarr[j] - newm);
                    l += p;
                    #pragma unroll
                    for (int d = 0; d < 32; d++) acc[d] += p * Vs[j][d];
                }
            }
            mrun = newm;
        }
        __syncthreads();
    }
    float inv = 1.f / l;
    float* xr = x + (b * 512 + qi) * 256 + h * 32;
    #pragma unroll
    for (int d = 0; d < 32; d++) xr[d] += acc[d] * inv;
}

// ---------------- deterministic global mean/std (ddof=1) + normalize ------------
__global__ void reduce_k(const float* __restrict__ e) {
    __shared__ double s1[256], s2[256];
    const int t = threadIdx.x;
    double s = 0.0, ss = 0.0;
    for (int i = blockIdx.x * 256 + t; i < 262144; i += 256 * 256) {
        double v = (double)e[i];
        s += v;
        ss += v * v;
    }
    s1[t] = s;
    s2[t] = ss;
    __syncthreads();
    for (int k = 128; k > 0; k >>= 1) {
        if (t < k) { s1[t] += s1[t + k]; s2[t] += s2[t + k]; }
        __syncthreads();
    }
    if (t == 0) { g_part[blockIdx.x] = s1[0]; g_part[256 + blockIdx.x] = s2[0]; }
}

__global__ void stats_k() {
    __shared__ double s1[256], s2[256];
    const int t = threadIdx.x;
    s1[t] = g_part[t];
    s2[t] = g_part[256 + t];
    __syncthreads();
    for (int k = 128; k > 0; k >>= 1) {
        if (t < k) { s1[t] += s1[t + k]; s2[t] += s2[t + k]; }
        __syncthreads();
    }
    if (t == 0) { g_sum = s1[0]; g_sumsq = s2[0]; }
}

__global__ void norm_k(float* e) {
    const double n = 262144.0;
    double mu = g_sum / n;
    double var = (g_sumsq - n * mu * mu) / (n - 1.0);
    float inv = (float)(1.0 / sqrt(var));
    float fmu = (float)mu;
    int i = blockIdx.x * 256 + threadIdx.x;
    e[i] = (e[i] - fmu) * inv + 1e-10f;
}

// ---------------- launch ----------------
extern "C" void kernel_launch(void* const* d_in, const int* in_sizes, int n_in,
                              void* d_out, int out_size) {
    const float* state   = (const float*)d_in[0];
    const float* conv_w1 = (const float*)d_in[1];
    const float* conv_b1 = (const float*)d_in[2];
    const float* conv_w2 = (const float*)d_in[3];
    const float* conv_b2 = (const float*)d_in[4];
    const float* conv_w3 = (const float*)d_in[5];
    const float* conv_b3 = (const float*)d_in[6];
    const float* pre_w   = (const float*)d_in[7];
    const float* pre_b   = (const float*)d_in[8];
    const float* pos_w   = (const float*)d_in[9];
    const float* ln1_g   = (const float*)d_in[10];
    const float* ln1_b   = (const float*)d_in[11];
    const float* enc_w   = (const float*)d_in[12];
    const float* enc_b   = (const float*)d_in[13];
    const float* ln2_g   = (const float*)d_in[14];
    const float* ln2_b   = (const float*)d_in[15];
    const float* ffn_w1  = (const float*)d_in[16];
    const float* ffn_b1  = (const float*)d_in[17];
    const float* ffn_w2  = (const float*)d_in[18];
    const float* ffn_b2  = (const float*)d_in[19];
    const float* emb_w   = (const float*)d_in[20];
    const float* emb_b   = (const float*)d_in[21];
    float* out = (float*)d_out;

    float *x1, *x2, *x3, *x, *xn, *cb, *hb;
    cudaGetSymbolAddress((void**)&x1, g_x1);
    cudaGetSymbolAddress((void**)&x2, g_x2);
    cudaGetSymbolAddress((void**)&x3, g_x3);
    cudaGetSymbolAddress((void**)&x,  g_x);
    cudaGetSymbolAddress((void**)&xn, g_xn);
    cudaGetSymbolAddress((void**)&cb, g_c);
    cudaGetSymbolAddress((void**)&hb, g_h);

    // conv stem: 96x120 -> 48x60 -> 24x30 -> 12x15
    conv_k<3><<<2880, 256>>>(state, conv_w1, conv_b1, x1, 96, 120, 48, 60);
    conv_k<16><<<768, 256>>>(x1, conv_w2, conv_b2, x2, 48, 60, 24, 30);
    conv_k<16><<<192, 256>>>(x2, conv_w3, conv_b3, x3, 24, 30, 12, 15);

    // pre-projection + positional  (tf32 tensor cores)
    gemm_k<1><<<dim3(4, 32), 256>>>(x3, pre_w, pre_b, pos_w, x, 1024, 256, 2880);

    for (int k = 0; k < 4; k++) {
        ln_k<<<1024, 256>>>(x, ln1_g + k * 256, ln1_b + k * 256, xn);
        gemm_k<0><<<dim3(12, 32), 256>>>(xn, enc_w + k * 256 * 768, enc_b + k * 768,
                                         nullptr, cb, 1024, 768, 256);
        attn_k<<<dim3(8, 16), 64>>>(cb, x);
        ln_k<<<1024, 256>>>(x, ln2_g + k * 256, ln2_b + k * 256, x);
        gemm_k<2><<<dim3(16, 32), 256>>>(x, ffn_w1 + k * 256 * 1024, ffn_b1 + k * 1024,
                                         nullptr, hb, 1024, 1024, 256);
        gemm_k<3><<<dim3(4, 32), 256>>>(hb, ffn_w2 + k * 1024 * 256, ffn_b2 + k * 256,
                                        x, x, 1024, 256, 1024);
    }

    gemm_k<0><<<dim3(4, 32), 256>>>(x, emb_w, emb_b, nullptr, out, 1024, 256, 256);

    reduce_k<<<256, 256>>>(out);
    stats_k<<<1, 256>>>();
    norm_k<<<1024, 256>>>(out);
}

// round 4
// speedup vs baseline: 1.6180x; 1.1071x over previous
#include <cuda_runtime.h>
#include <math.h>

// ---------------- scratch (device globals; no allocation allowed) ----------------
__device__ float g_x1[1024 * 16 * 48 * 60];   // conv1 out
__device__ float g_x2[1024 * 16 * 24 * 30];   // conv2 out
__device__ float g_x3[1024 * 16 * 12 * 15];   // conv3 out (= tokens x 2880)
__device__ float g_x [1024 * 256];            // residual stream
__device__ float g_xn[1024 * 256];            // ln1 output
__device__ float g_c [1024 * 768];            // qkv
__device__ float g_h [1024 * 1024];           // ffn hidden
__device__ float g_sp[2 * 1024 * 1024];       // split-K partials (max 2M floats)
__device__ unsigned g_cnt[512];               // per-tile arrival counters (reset by last block)
__device__ double g_part[512];                // partial sums / sumsq
__device__ double g_sum, g_sumsq;

// ---------------- conv: stride 2, pad 1, 4x4, relu(out + bias) ----------------
template <int CIN>
__global__ void __launch_bounds__(256) conv_k(
    const float* __restrict__ in, const float* __restrict__ w,
    const float* __restrict__ bias, float* __restrict__ out,
    int Hin, int Win, int Hout, int Wout) {
    __shared__ float ws[CIN * 16 * 16];   // [widx][co]
    __shared__ float bs[16];
    for (int i = threadIdx.x; i < CIN * 16 * 16; i += blockDim.x) {
        int widx = i >> 4, co = i & 15;
        ws[i] = w[co * CIN * 16 + widx];
    }
    if (threadIdx.x < 16) bs[threadIdx.x] = bias[threadIdx.x];
    __syncthreads();

    const int wg = (Wout + 3) >> 2;
    int idx = blockIdx.x * blockDim.x + threadIdx.x;
    int owg = idx % wg;
    int oh  = (idx / wg) % Hout;
    int n   = idx / (wg * Hout);
    if (n >= 1024) return;

    float acc[16][4];
    #pragma unroll
    for (int co = 0; co < 16; co++)
        #pragma unroll
        for (int p = 0; p < 4; p++) acc[co][p] = 0.f;

    const float* inp = in + n * CIN * Hin * Win;
    const int iwb = owg * 8 - 1;
    #pragma unroll 1
    for (int ci = 0; ci < CIN; ci++) {
        #pragma unroll
        for (int kh = 0; kh < 4; kh++) {
            int ih = oh * 2 - 1 + kh;
            if (ih < 0 || ih >= Hin) continue;
            const float* irow = inp + (ci * Hin + ih) * Win;
            float vin[10];
            #pragma unroll
            for (int j = 0; j < 10; j++) {
                int iw = iwb + j;
                vin[j] = (iw >= 0 && iw < Win) ? irow[iw] : 0.f;
            }
            #pragma unroll
            for (int kw = 0; kw < 4; kw++) {
                int widx = (ci * 4 + kh) * 4 + kw;
                const float4* w4 = (const float4*)&ws[widx << 4];
                float4 w0 = w4[0], w1 = w4[1], w2 = w4[2], w3 = w4[3];
                #pragma unroll
                for (int p = 0; p < 4; p++) {
                    float v = vin[2 * p + kw];
                    acc[0][p]  += w0.x * v; acc[1][p]  += w0.y * v;
                    acc[2][p]  += w0.z * v; acc[3][p]  += w0.w * v;
                    acc[4][p]  += w1.x * v; acc[5][p]  += w1.y * v;
                    acc[6][p]  += w1.z * v; acc[7][p]  += w1.w * v;
                    acc[8][p]  += w2.x * v; acc[9][p]  += w2.y * v;
                    acc[10][p] += w2.z * v; acc[11][p] += w2.w * v;
                    acc[12][p] += w3.x * v; acc[13][p] += w3.y * v;
                    acc[14][p] += w3.z * v; acc[15][p] += w3.w * v;
                }
            }
        }
    }
    int obase = n * 16 * Hout * Wout;
    #pragma unroll
    for (int co = 0; co < 16; co++) {
        #pragma unroll
        for (int p = 0; p < 4; p++) {
            int ow = owg * 4 + p;
            if (ow < Wout)
                out[obase + (co * Hout + oh) * Wout + ow] = fmaxf(acc[co][p] + bs[co], 0.f);
        }
    }
}

// ---------------- tf32 tensor-core GEMM with split-K ----------------
// Block tile 32x64, 256 threads (8 warps as 2x4), warp tile 16x16.
// blockIdx.z = K-split index; last-arriving block per tile reduces S partials
// (fixed order s=0..S-1 -> deterministic) and applies the epilogue.
// EPI 0: +bias   EPI 1: +bias+pos[(m%512)*N+n]   EPI 2: gelu(+bias)   EPI 3: +bias+extra
__device__ __forceinline__ unsigned f2tf(float f) {
    unsigned u;
    asm("cvt.rna.tf32.f32 %0, %1;" : "=r"(u) : "f"(f));
    return u;
}
__device__ __forceinline__ void mma_tf32(float c[4], unsigned a0, unsigned a1,
                                         unsigned a2, unsigned a3,
                                         unsigned b0, unsigned b1) {
    asm volatile(
        "mma.sync.aligned.m16n8k8.row.col.f32.tf32.tf32.f32 "
        "{%0,%1,%2,%3}, {%4,%5,%6,%7}, {%8,%9}, {%0,%1,%2,%3};\n"
        : "+f"(c[0]), "+f"(c[1]), "+f"(c[2]), "+f"(c[3])
        : "r"(a0), "r"(a1), "r"(a2), "r"(a3), "r"(b0), "r"(b1));
}

template <int EPI>
__device__ __forceinline__ float epi_apply(float v, int m, int n, int N,
                                           const float* __restrict__ extra) {
    if (EPI == 1) v += extra[(m & 511) * N + n];
    if (EPI == 2) v = v * normcdff(v);
    if (EPI == 3) v += extra[m * N + n];
    return v;
}

template <int EPI>
__global__ void __launch_bounds__(256) gemm_k(
    const float* __restrict__ A, const float* __restrict__ B,
    const float* __restrict__ bias, const float* __restrict__ extra,
    float* __restrict__ C, int M, int N, int K, int S, int Kc) {
    __shared__ unsigned As[32][36];   // [m][k]
    __shared__ unsigned Bs[32][68];   // [k][n]

    const int t = threadIdx.x;
    const int m0 = blockIdx.y * 32, n0 = blockIdx.x * 64;
    const int z = blockIdx.z;
    const int kb0 = z * Kc;
    const int warp = t >> 5, lane = t & 31;
    const int g = lane >> 2, tig = lane & 3;
    const int wm = (warp >> 2) * 16;
    const int wn = (warp & 3) * 16;

    float acc[2][4];
    #pragma unroll
    for (int nf = 0; nf < 2; nf++)
        #pragma unroll
        for (int r = 0; r < 4; r++) acc[nf][r] = 0.f;

    const int a_row = t >> 3, a_col = (t & 7) * 4;
    const int b_row = t >> 4, b_col = (t & 15) * 4;
    const int NC = Kc >> 5;
    const float* Ab = A + kb0;
    const float* Bb = B + (size_t)kb0 * N;
    float4 ra, rb0, rb1;

    ra  = *(const float4*)&Ab[(m0 + a_row) * K + a_col];
    rb0 = *(const float4*)&Bb[b_row * N + n0 + b_col];
    rb1 = *(const float4*)&Bb[(b_row + 16) * N + n0 + b_col];

    for (int c = 0; c < NC; c++) {
        {
            unsigned* p = &As[a_row][a_col];
            p[0] = f2tf(ra.x); p[1] = f2tf(ra.y); p[2] = f2tf(ra.z); p[3] = f2tf(ra.w);
            unsigned* q0 = &Bs[b_row][b_col];
            q0[0] = f2tf(rb0.x); q0[1] = f2tf(rb0.y); q0[2] = f2tf(rb0.z); q0[3] = f2tf(rb0.w);
            unsigned* q1 = &Bs[b_row + 16][b_col];
            q1[0] = f2tf(rb1.x); q1[1] = f2tf(rb1.y); q1[2] = f2tf(rb1.z); q1[3] = f2tf(rb1.w);
        }
        __syncthreads();

        if (c + 1 < NC) {
            int k0 = (c + 1) * 32;
            ra  = *(const float4*)&Ab[(m0 + a_row) * K + k0 + a_col];
            rb0 = *(const float4*)&Bb[(k0 + b_row) * N + n0 + b_col];
            rb1 = *(const float4*)&Bb[(k0 + b_row + 16) * N + n0 + b_col];
        }

        #pragma unroll
        for (int ks = 0; ks < 4; ks++) {
            int k8 = ks * 8;
            unsigned a0 = As[wm + g][k8 + tig];
            unsigned a1 = As[wm + g + 8][k8 + tig];
            unsigned a2 = As[wm + g][k8 + tig + 4];
            unsigned a3 = As[wm + g + 8][k8 + tig + 4];
            #pragma unroll
            for (int nf = 0; nf < 2; nf++) {
                int nc = wn + nf * 8 + g;
                unsigned b0 = Bs[k8 + tig][nc];
                unsigned b1 = Bs[k8 + tig + 4][nc];
                mma_tf32(acc[nf], a0, a1, a2, a3, b0, b1);
            }
        }
        __syncthreads();
    }

    if (S == 1) {
        #pragma unroll
        for (int half = 0; half < 2; half++) {
            int m = m0 + wm + g + half * 8;
            #pragma unroll
            for (int nf = 0; nf < 2; nf++) {
                int n = n0 + wn + nf * 8 + 2 * tig;
                float v0 = epi_apply<EPI>(acc[nf][2 * half] + bias[n], m, n, N, extra);
                float v1 = epi_apply<EPI>(acc[nf][2 * half + 1] + bias[n + 1], m, n + 1, N, extra);
                *(float2*)&C[m * N + n] = make_float2(v0, v1);
            }
        }
        return;
    }

    // ---- split-K: write partial, last block reduces ----
    float* pz = g_sp + (size_t)z * M * N;
    #pragma unroll
    for (int half = 0; half < 2; half++) {
        int m = m0 + wm + g + half * 8;
        #pragma unroll
        for (int nf = 0; nf < 2; nf++) {
            int n = n0 + wn + nf * 8 + 2 * tig;
            *(float2*)&pz[m * N + n] = make_float2(acc[nf][2 * half], acc[nf][2 * half + 1]);
        }
    }
    __threadfence();
    __syncthreads();
    __shared__ unsigned s_old;
    const int tile = blockIdx.y * gridDim.x + blockIdx.x;
    if (t == 0) s_old = atomicAdd(&g_cnt[tile], 1);
    __syncthreads();
    if (s_old != (unsigned)(S - 1)) return;
    __threadfence();

    #pragma unroll
    for (int half = 0; half < 2; half++) {
        int m = m0 + wm + g + half * 8;
        #pragma unroll
        for (int nf = 0; nf < 2; nf++) {
            int n = n0 + wn + nf * 8 + 2 * tig;
            float v0 = bias[n], v1 = bias[n + 1];
            for (int s = 0; s < S; s++) {
                float2 pv = *(const float2*)&g_sp[(size_t)s * M * N + m * N + n];
                v0 += pv.x; v1 += pv.y;
            }
            v0 = epi_apply<EPI>(v0, m, n, N, extra);
            v1 = epi_apply<EPI>(v1, m, n + 1, N, extra);
            *(float2*)&C[m * N + n] = make_float2(v0, v1);
        }
    }
    if (t == 0) g_cnt[tile] = 0;
}

// ---------------- layernorm: one warp per row, shuffle reductions ----------------
__global__ void __launch_bounds__(256) ln_k(
    const float* __restrict__ in, const float* __restrict__ gw,
    const float* __restrict__ bw, float* __restrict__ out) {
    const int t = threadIdx.x, warp = t >> 5, lane = t & 31;
    const int row = blockIdx.x * 8 + warp;
    const float4* r = (const float4*)(in + row * 256);
    float4 v0 = r[lane], v1 = r[lane + 32];
    float s = v0.x + v0.y + v0.z + v0.w + v1.x + v1.y + v1.z + v1.w;
    #pragma unroll
    for (int o = 16; o > 0; o >>= 1) s += __shfl_xor_sync(0xffffffffu, s, o);
    float mu = s * (1.f / 256.f);
    float d0x = v0.x - mu, d0y = v0.y - mu, d0z = v0.z - mu, d0w = v0.w - mu;
    float d1x = v1.x - mu, d1y = v1.y - mu, d1z = v1.z - mu, d1w = v1.w - mu;
    float ss = d0x * d0x + d0y * d0y + d0z * d0z + d0w * d0w
             + d1x * d1x + d1y * d1y + d1z * d1z + d1w * d1w;
    #pragma unroll
    for (int o = 16; o > 0; o >>= 1) ss += __shfl_xor_sync(0xffffffffu, ss, o);
    float inv = rsqrtf(ss * (1.f / 256.f) + 1e-5f);
    const float4* g4 = (const float4*)gw;
    const float4* b4 = (const float4*)bw;
    float4 ga = g4[lane], gb = g4[lane + 32];
    float4 ba = b4[lane], bb = b4[lane + 32];
    float4* o4 = (float4*)(out + row * 256);
    o4[lane] = make_float4(d0x * inv * ga.x + ba.x, d0y * inv * ga.y + ba.y,
                           d0z * inv * ga.z + ba.z, d0w * inv * ga.w + ba.w);
    o4[lane + 32] = make_float4(d1x * inv * gb.x + bb.x, d1y * inv * gb.y + bb.y,
                                d1z * inv * gb.z + bb.z, d1w * inv * gb.w + bb.w);
}

// ---------------- causal attention: 2 threads per query (d-split) ----------------
__global__ void __launch_bounds__(128) attn_k(const float* __restrict__ c,
                                              float* __restrict__ x) {
    __shared__ float Ks[32][32];
    __shared__ float Vs[32][32];
    const int t = threadIdx.x;            // 128 threads
    const int qt = blockIdx.x;            // 8 query tiles of 64
    const int bh = blockIdx.y;            // 16 (b,h)
    const int b = bh >> 3, h = bh & 7;
    const int qi = qt * 64 + (t & 63);
    const int dhalf = t >> 6;             // 0 or 1: V dims [dhalf*16, +16)
    const float* crow = c + (b * 512 + qi) * 768 + h * 32;

    const float SC = 0.17677669529663687f;  // 1/sqrt(32)
    float q[32];
    #pragma unroll
    for (int d4 = 0; d4 < 8; d4++) {
        float4 qv = *(const float4*)(crow + d4 * 4);
        q[4 * d4 + 0] = qv.x * SC;
        q[4 * d4 + 1] = qv.y * SC;
        q[4 * d4 + 2] = qv.z * SC;
        q[4 * d4 + 3] = qv.w * SC;
    }
    float acc[16];
    #pragma unroll
    for (int d = 0; d < 16; d++) acc[d] = 0.f;
    float mrun = -1e30f, l = 0.f;

    const int kend = qt * 64 + 63;
    const int jj = t >> 2, q8 = (t & 3) * 8;
    for (int kb = 0; kb <= kend; kb += 32) {
        const float* kr = c + (b * 512 + kb + jj) * 768 + 256 + h * 32 + q8;
        *(float4*)&Ks[jj][q8]     = *(const float4*)(kr);
        *(float4*)&Ks[jj][q8 + 4] = *(const float4*)(kr + 4);
        *(float4*)&Vs[jj][q8]     = *(const float4*)(kr + 256);
        *(float4*)&Vs[jj][q8 + 4] = *(const float4*)(kr + 260);
        __syncthreads();
        if (kb <= qi) {
            int jmax = qi - kb;
            if (jmax > 31) jmax = 31;
            float sarr[32];
            float tmax = -1e30f;
            #pragma unroll
            for (int j = 0; j < 32; j++) {
                if (j <= jmax) {
                    float s = 0.f;
                    #pragma unroll
                    for (int d = 0; d < 32; d++) s += q[d] * Ks[j][d];
                    sarr[j] = s;
                    tmax = fmaxf(tmax, s);
                }
            }
            float newm = fmaxf(mrun, tmax);
            float alpha = __expf(mrun - newm);
            l *= alpha;
            #pragma unroll
            for (int d = 0; d < 16; d++) acc[d] *= alpha;
            #pragma unroll
            for (int j = 0; j < 32; j++) {
                if (j <= jmax) {
                    float p = __expf(sarr[j] - newm);
                    l += p;
                    #pragma unroll
                    for (int d = 0; d < 16; d++) acc[d] += p * Vs[j][dhalf * 16 + d];
                }
            }
            mrun = newm;
        }
        __syncthreads();
    }
    float inv = 1.f / l;
    float* xr = x + (b * 512 + qi) * 256 + h * 32 + dhalf * 16;
    #pragma unroll
    for (int d = 0; d < 16; d++) xr[d] += acc[d] * inv;
}

// ---------------- deterministic global mean/std (ddof=1) + normalize ------------
__global__ void reduce_k(const float* __restrict__ e) {
    __shared__ double s1[256], s2[256];
    const int t = threadIdx.x;
    double s = 0.0, ss = 0.0;
    for (int i = blockIdx.x * 256 + t; i < 262144; i += 256 * 256) {
        double v = (double)e[i];
        s += v;
        ss += v * v;
    }
    s1[t] = s;
    s2[t] = ss;
    __syncthreads();
    for (int k = 128; k > 0; k >>= 1) {
        if (t < k) { s1[t] += s1[t + k]; s2[t] += s2[t + k]; }
        __syncthreads();
    }
    if (t == 0) { g_part[blockIdx.x] = s1[0]; g_part[256 + blockIdx.x] = s2[0]; }
}

__global__ void stats_k() {
    __shared__ double s1[256], s2[256];
    const int t = threadIdx.x;
    s1[t] = g_part[t];
    s2[t] = g_part[256 + t];
    __syncthreads();
    for (int k = 128; k > 0; k >>= 1) {
        if (t < k) { s1[t] += s1[t + k]; s2[t] += s2[t + k]; }
        __syncthreads();
    }
    if (t == 0) { g_sum = s1[0]; g_sumsq = s2[0]; }
}

__global__ void norm_k(float* e) {
    const double n = 262144.0;
    double mu = g_sum / n;
    double var = (g_sumsq - n * mu * mu) / (n - 1.0);
    float inv = (float)(1.0 / sqrt(var));
    float fmu = (float)mu;
    int i = blockIdx.x * 256 + threadIdx.x;
    e[i] = (e[i] - fmu) * inv + 1e-10f;
}

// ---------------- launch ----------------
extern "C" void kernel_launch(void* const* d_in, const int* in_sizes, int n_in,
                              void* d_out, int out_size) {
    const float* state   = (const float*)d_in[0];
    const float* conv_w1 = (const float*)d_in[1];
    const float* conv_b1 = (const float*)d_in[2];
    const float* conv_w2 = (const float*)d_in[3];
    const float* conv_b2 = (const float*)d_in[4];
    const float* conv_w3 = (const float*)d_in[5];
    const float* conv_b3 = (const float*)d_in[6];
    const float* pre_w   = (const float*)d_in[7];
    const float* pre_b   = (const float*)d_in[8];
    const float* pos_w   = (const float*)d_in[9];
    const float* ln1_g   = (const float*)d_in[10];
    const float* ln1_b   = (const float*)d_in[11];
    const float* enc_w   = (const float*)d_in[12];
    const float* enc_b   = (const float*)d_in[13];
    const float* ln2_g   = (const float*)d_in[14];
    const float* ln2_b   = (const float*)d_in[15];
    const float* ffn_w1  = (const float*)d_in[16];
    const float* ffn_b1  = (const float*)d_in[17];
    const float* ffn_w2  = (const float*)d_in[18];
    const float* ffn_b2  = (const float*)d_in[19];
    const float* emb_w   = (const float*)d_in[20];
    const float* emb_b   = (const float*)d_in[21];
    float* out = (float*)d_out;

    float *x1, *x2, *x3, *x, *xn, *cb, *hb;
    cudaGetSymbolAddress((void**)&x1, g_x1);
    cudaGetSymbolAddress((void**)&x2, g_x2);
    cudaGetSymbolAddress((void**)&x3, g_x3);
    cudaGetSymbolAddress((void**)&x,  g_x);
    cudaGetSymbolAddress((void**)&xn, g_xn);
    cudaGetSymbolAddress((void**)&cb, g_c);
    cudaGetSymbolAddress((void**)&hb, g_h);

    // conv stem: 96x120 -> 48x60 -> 24x30 -> 12x15
    conv_k<3><<<2880, 256>>>(state, conv_w1, conv_b1, x1, 96, 120, 48, 60);
    conv_k<16><<<768, 256>>>(x1, conv_w2, conv_b2, x2, 48, 60, 24, 30);
    conv_k<16><<<192, 256>>>(x2, conv_w3, conv_b3, x3, 24, 30, 12, 15);

    // pre-projection + positional  (split-K tf32)
    gemm_k<1><<<dim3(4, 32, 6), 256>>>(x3, pre_w, pre_b, pos_w, x,
                                       1024, 256, 2880, 6, 480);

    for (int k = 0; k < 4; k++) {
        ln_k<<<128, 256>>>(x, ln1_g + k * 256, ln1_b + k * 256, xn);
        gemm_k<0><<<dim3(12, 32, 2), 256>>>(xn, enc_w + k * 256 * 768, enc_b + k * 768,
                                            nullptr, cb, 1024, 768, 256, 2, 128);
        attn_k<<<dim3(8, 16), 128>>>(cb, x);
        ln_k<<<128, 256>>>(x, ln2_g + k * 256, ln2_b + k * 256, x);
        gemm_k<2><<<dim3(16, 32, 2), 256>>>(x, ffn_w1 + k * 256 * 1024, ffn_b1 + k * 1024,
                                            nullptr, hb, 1024, 1024, 256, 2, 128);
        gemm_k<3><<<dim3(4, 32, 4), 256>>>(hb, ffn_w2 + k * 1024 * 256, ffn_b2 + k * 256,
                                           x, x, 1024, 256, 1024, 4, 256);
    }

    gemm_k<0><<<dim3(4, 32, 4), 256>>>(x, emb_w, emb_b, nullptr, out,
                                       1024, 256, 256, 4, 64);

    reduce_k<<<256, 256>>>(out);
    stats_k<<<1, 256>>>();
    norm_k<<<1024, 256>>>(out);
}